// round 12
// baseline (speedup 1.0000x reference)
#include <cuda_runtime.h>
#include <cstdint>

#define TOKENS  131072
#define KCODES  512
#define DIM     64
#define TILE_M  256
#define NTILES  (TOKENS / TILE_M)   /* 512 */
#define NCTA    148
#define TPB     512
#define NHALF   256
#define MAXSLOT 4

/* ---- smem layout (bytes) ---- */
#define SM_B     0                            /* 256 rows x 576B split quads */
#define SM_A     147456                       /* 256 rows x 288B raw pairs   */
#define SM_WSQ   (SM_A + TILE_M * 288)        /* 221184: 512 f32             */
#define SM_SX    (SM_WSQ + 2048)              /* 223232: 256 f32 (red alias) */
#define SM_BEST  (SM_SX + 1024)               /* 224256: 1024 f32            */
#define SM_IDX   (SM_BEST + 4096)             /* 228352: 1024 u16            */
#define SM_HIST  (SM_IDX + 2048)              /* 230400: 512 int             */
#define SMEM_TOTAL (SM_HIST + 2048)           /* 232448 = 227 KB max         */

__device__ int   g_counts[KCODES];
__device__ float g_msep[NCTA];

__device__ __forceinline__ uint32_t f2tf32(float v) {
    uint32_t r;
    asm("cvt.rna.tf32.f32 %0, %1;" : "=r"(r) : "f"(v));
    return r;
}
__device__ __forceinline__ void tf32split(float v, uint32_t& h, uint32_t& l) {
    h = f2tf32(v);
    l = f2tf32(v - __uint_as_float(h));
}

__device__ __forceinline__ void mma_tf32(float c[4], const uint32_t a[4],
                                         uint32_t b0, uint32_t b1)
{
    asm volatile(
        "mma.sync.aligned.m16n8k8.row.col.f32.tf32.tf32.f32 "
        "{%0,%1,%2,%3}, {%4,%5,%6,%7}, {%8,%9}, {%0,%1,%2,%3};"
        : "+f"(c[0]), "+f"(c[1]), "+f"(c[2]), "+f"(c[3])
        : "r"(a[0]), "r"(a[1]), "r"(a[2]), "r"(a[3]), "r"(b0), "r"(b1));
}

__global__ void __launch_bounds__(KCODES, 1) vq_init()
{
    g_counts[threadIdx.x] = 0;
}

/* ---------------- main (persistent, 148 CTAs x 512 thr) ---------------- */
__global__ void __launch_bounds__(TPB, 1)
vq_main(const float* __restrict__ x, const float* __restrict__ w,
        float* __restrict__ out)
{
    extern __shared__ char smem[];
    float*          s_wsq  = (float*)(smem + SM_WSQ);
    float*          s_sx   = (float*)(smem + SM_SX);
    float*          s_best = (float*)(smem + SM_BEST);
    unsigned short* s_idx  = (unsigned short*)(smem + SM_IDX);
    int*            s_hist = (int*)(smem + SM_HIST);
    float*          s_red  = (float*)(smem + SM_SX);   /* alias: sx dead then */

    const int tid  = threadIdx.x;
    const int wid  = tid >> 5;
    const int lane = tid & 31;
    const int qr   = lane >> 2;
    const int qp   = lane & 3;
    const int bid  = blockIdx.x;

    for (int i = tid; i < KCODES; i += TPB) s_hist[i] = 0;
    for (int i = tid; i < MAXSLOT * TILE_M; i += TPB) {
        s_best[i] = __int_as_float(0x7f800000);
        s_idx[i]  = 0;
    }
    /* wsq: one row per thread, sequential fmaf chain (matches ref) */
    {
        const float* wr = w + (size_t)tid * DIM;
        float sq = 0.f;
        #pragma unroll
        for (int c = 0; c < DIM; c++) sq = fmaf(wr[c], wr[c], sq);
        s_wsq[tid] = sq;
    }
    __syncthreads();

    int nslots = 0;

    #pragma unroll 1
    for (int half = 0; half < 2; half++) {
        const int nbase = half * NHALF;

        /* ---- pack B half: tf32 split quads {bh,bh+4,bl,bl+4} ---- */
        if (tid < NHALF) {
            const float* wr = w + (size_t)(nbase + tid) * DIM;
            float4* br = (float4*)(smem + SM_B + (size_t)tid * 576);
            #pragma unroll
            for (int k = 0; k < 8; k++) {
                float4 v0 = *(const float4*)(wr + k * 8);
                float4 v1 = *(const float4*)(wr + k * 8 + 4);
                uint32_t h0, l0, h1, l1;
                tf32split(v0.x, h0, l0); tf32split(v1.x, h1, l1);
                br[k * 4 + 0] = make_float4(__uint_as_float(h0), __uint_as_float(h1),
                                            __uint_as_float(l0), __uint_as_float(l1));
                tf32split(v0.y, h0, l0); tf32split(v1.y, h1, l1);
                br[k * 4 + 1] = make_float4(__uint_as_float(h0), __uint_as_float(h1),
                                            __uint_as_float(l0), __uint_as_float(l1));
                tf32split(v0.z, h0, l0); tf32split(v1.z, h1, l1);
                br[k * 4 + 2] = make_float4(__uint_as_float(h0), __uint_as_float(h1),
                                            __uint_as_float(l0), __uint_as_float(l1));
                tf32split(v0.w, h0, l0); tf32split(v1.w, h1, l1);
                br[k * 4 + 3] = make_float4(__uint_as_float(h0), __uint_as_float(h1),
                                            __uint_as_float(l0), __uint_as_float(l1));
            }
        }
        __syncthreads();

        int slot = 0;
        #pragma unroll 1
        for (int tile = bid; tile < NTILES; tile += NCTA, slot++) {
            const int T0 = tile * TILE_M;

            /* ---- gather tokens (threads 0..255), raw pairs + s chain ---- */
            if (tid < TILE_M) {
                const int b  = T0 >> 12;
                const int hw = (T0 & 4095) + tid;
                const float* xb = x + (size_t)b * (DIM * 4096) + hw;
                float2* ar = (float2*)(smem + SM_A + (size_t)tid * 288);
                float s = 0.f;
                #pragma unroll
                for (int g8 = 0; g8 < 8; g8++) {
                    float v[8];
                    #pragma unroll
                    for (int j = 0; j < 8; j++)
                        v[j] = xb[(size_t)(g8 * 8 + j) * 4096];
                    #pragma unroll
                    for (int j = 0; j < 8; j++) s = fmaf(v[j], v[j], s);
                    #pragma unroll
                    for (int j = 0; j < 4; j++)
                        ar[g8 * 4 + j] = make_float2(v[j], v[j + 4]);
                }
                s_sx[tid] = s;
            }
            __syncthreads();

            /* ---- warp stripe: 16 tokens x 256 codes (this half) ---- */
            {
                const int r0 = wid * 16 + qr, r1 = r0 + 8;
                const float2* pa0 = (const float2*)(smem + SM_A + (size_t)r0 * 288) + qp;
                const float2* pa1 = (const float2*)(smem + SM_A + (size_t)r1 * 288) + qp;

                uint32_t Ah[8][4], Al[8][4];
                #pragma unroll
                for (int k = 0; k < 8; k++) {
                    float2 p0 = pa0[k * 4];
                    float2 p1 = pa1[k * 4];
                    tf32split(p0.x, Ah[k][0], Al[k][0]);
                    tf32split(p1.x, Ah[k][1], Al[k][1]);
                    tf32split(p0.y, Ah[k][2], Al[k][2]);
                    tf32split(p1.y, Ah[k][3], Al[k][3]);
                }

                const float sx0 = s_sx[r0];
                const float sx1 = s_sx[r1];
                float best0 = __int_as_float(0x7f800000), best1 = best0;
                int   bi0 = 0, bi1 = 0;

                #pragma unroll 2
                for (int n0 = 0; n0 < NHALF; n0 += 8) {
                    float c0[4] = {0.f, 0.f, 0.f, 0.f};
                    float c1[4] = {0.f, 0.f, 0.f, 0.f};
                    float c2[4] = {0.f, 0.f, 0.f, 0.f};
                    const uint4* pb =
                        (const uint4*)(smem + SM_B + (size_t)(n0 + qr) * 576) + qp;
                    #pragma unroll
                    for (int k = 0; k < 8; k++) {
                        uint4 q = pb[k * 4];           /* {bh0,bh1,bl0,bl1} */
                        mma_tf32(c0, Ah[k], q.x, q.y); /* hi*hi */
                        mma_tf32(c1, Al[k], q.x, q.y); /* lo*hi */
                        mma_tf32(c2, Ah[k], q.z, q.w); /* hi*lo */
                    }
                    const int gj = nbase + n0 + 2 * qp;
                    const float2 wsq2 = *(const float2*)(s_wsq + gj);
                    const float d00 = fmaf(-2.f, (c0[0] + c1[0]) + c2[0], sx0) + wsq2.x;
                    const float d01 = fmaf(-2.f, (c0[1] + c1[1]) + c2[1], sx0) + wsq2.y;
                    const float d10 = fmaf(-2.f, (c0[2] + c1[2]) + c2[2], sx1) + wsq2.x;
                    const float d11 = fmaf(-2.f, (c0[3] + c1[3]) + c2[3], sx1) + wsq2.y;
                    if (d00 < best0) { best0 = d00; bi0 = gj; }
                    if (d01 < best0) { best0 = d01; bi0 = gj + 1; }
                    if (d10 < best1) { best1 = d10; bi1 = gj; }
                    if (d11 < best1) { best1 = d11; bi1 = gj + 1; }
                }

                /* cross-quad reduce, first-index tie-break */
                #pragma unroll
                for (int o = 1; o <= 2; o <<= 1) {
                    float ob0 = __shfl_xor_sync(0xffffffffu, best0, o);
                    int   oi0 = __shfl_xor_sync(0xffffffffu, bi0, o);
                    float ob1 = __shfl_xor_sync(0xffffffffu, best1, o);
                    int   oi1 = __shfl_xor_sync(0xffffffffu, bi1, o);
                    if (ob0 < best0 || (ob0 == best0 && oi0 < bi0)) { best0 = ob0; bi0 = oi0; }
                    if (ob1 < best1 || (ob1 == best1 && oi1 < bi1)) { best1 = ob1; bi1 = oi1; }
                }
                /* merge with running best (halves ascend: ties keep stored) */
                if (qp == 0) {
                    const int o0 = slot * TILE_M + r0;
                    const int o1 = slot * TILE_M + r1;
                    if (best0 < s_best[o0]) { s_best[o0] = best0; s_idx[o0] = (unsigned short)bi0; }
                    if (best1 < s_best[o1]) { s_best[o1] = best1; s_idx[o1] = (unsigned short)bi1; }
                }
            }
            __syncthreads();
        }
        nslots = slot;
    }

    /* ---- epilogue: out = x_lin + (w[idx]-x_lin), fused MSE + hist ---- */
    float mse_acc = 0.f;
    #pragma unroll 1
    for (int slot = 0; slot < nslots; slot++) {
        const int T0 = (bid + slot * NCTA) * TILE_M;
        if (tid < TILE_M) {
            const int g    = T0 + tid;
            const int bidx = (int)s_idx[slot * TILE_M + tid];
            const float4* wb = (const float4*)(w + (size_t)bidx * DIM);
            const float4* xl = (const float4*)(x + (size_t)g * DIM);
            float4*       o4 = (float4*)(out + (size_t)g * DIM);
            float mse = 0.f;
            #pragma unroll
            for (int i = 0; i < DIM / 4; i++) {
                float4 wv = wb[i];
                float4 xv = xl[i];
                float d0 = wv.x - xv.x, d1 = wv.y - xv.y;
                float d2 = wv.z - xv.z, d3 = wv.w - xv.w;
                mse = fmaf(d0, d0, mse); mse = fmaf(d1, d1, mse);
                mse = fmaf(d2, d2, mse); mse = fmaf(d3, d3, mse);
                float4 ov;
                ov.x = xv.x + d0; ov.y = xv.y + d1;
                ov.z = xv.z + d2; ov.w = xv.w + d3;
                o4[i] = ov;
            }
            mse_acc += mse;
            atomicAdd(&s_hist[bidx], 1);
        }
    }
    __syncthreads();   /* sx dead -> s_red alias safe */

    /* ---- block MSE reduce (warps 0..7 hold data) ---- */
    #pragma unroll
    for (int o = 16; o > 0; o >>= 1)
        mse_acc += __shfl_xor_sync(0xffffffffu, mse_acc, o);
    if (lane == 0) s_red[wid] = mse_acc;
    __syncthreads();
    if (tid == 0) {
        float t = 0.f;
        #pragma unroll
        for (int i = 0; i < TPB / 32; i++) t += s_red[i];
        g_msep[bid] = t;
    }

    /* ---- flush histogram ---- */
    for (int i = tid; i < KCODES; i += TPB) {
        int c = s_hist[i];
        if (c) atomicAdd(&g_counts[i], c);
    }
}

/* ---------------- final scalars ---------------- */
__global__ void __launch_bounds__(512, 1)
vq_final(float* __restrict__ out)
{
    __shared__ float sred[16];
    const int tid = threadIdx.x;

    float m = (tid < NCTA) ? g_msep[tid] : 0.f;
    #pragma unroll
    for (int o = 16; o > 0; o >>= 1)
        m += __shfl_xor_sync(0xffffffffu, m, o);
    if ((tid & 31) == 0) sred[tid >> 5] = m;
    __syncthreads();
    float mt = 0.f;
    if (tid == 0) {
        #pragma unroll
        for (int i = 0; i < 16; i++) mt += sred[i];
    }
    __syncthreads();

    float p = (float)g_counts[tid] * (1.0f / (float)TOKENS);
    float e = p * logf(p + 1e-10f);
    #pragma unroll
    for (int o = 16; o > 0; o >>= 1)
        e += __shfl_xor_sync(0xffffffffu, e, o);
    if ((tid & 31) == 0) sred[tid >> 5] = e;
    __syncthreads();
    if (tid == 0) {
        float et = 0.f;
        #pragma unroll
        for (int i = 0; i < 16; i++) et += sred[i];
        out[(size_t)TOKENS * DIM]     = 1.25f * (mt / (float)(TOKENS * DIM));
        out[(size_t)TOKENS * DIM + 1] = expf(-et);
    }
}

extern "C" void kernel_launch(void* const* d_in, const int* in_sizes, int n_in,
                              void* d_out, int out_size)
{
    const float* x = (const float*)d_in[0];
    const float* w = (const float*)d_in[1];
    if (n_in >= 2 && in_sizes[0] == KCODES * DIM && in_sizes[1] == TOKENS * DIM) {
        const float* t = x; x = w; w = t;
    }
    float* out = (float*)d_out;

    (void)cudaFuncSetAttribute(vq_main,
                               cudaFuncAttributeMaxDynamicSharedMemorySize,
                               SMEM_TOTAL);

    vq_init<<<1, KCODES>>>();
    vq_main<<<NCTA, TPB, SMEM_TOTAL>>>(x, w, out);
    vq_final<<<1, 512>>>(out);
}

// round 14
// speedup vs baseline: 1.0051x; 1.0051x over previous
#include <cuda_runtime.h>
#include <cstdint>

#define TOKENS  131072
#define KCODES  512
#define DIM     64
#define TILE_M  256
#define NTILES  (TOKENS / TILE_M)   /* 512 */
#define NCTA    148
#define TPB     512
#define NHALF   256
#define MAXSLOT 4

/* ---- smem layout (bytes) ---- */
#define SM_B     0                            /* 256 rows x 576B split quads */
#define SM_A     147456                       /* 256 rows x 288B raw pairs   */
#define SM_WSQ   (SM_A + TILE_M * 288)        /* 221184: 512 f32             */
#define SM_SX    (SM_WSQ + 2048)              /* 223232: 256 f32 (red alias) */
#define SM_BEST  (SM_SX + 1024)               /* 224256: 1024 f32            */
#define SM_IDX   (SM_BEST + 4096)             /* 228352: 1024 u16            */
#define SM_HIST  (SM_IDX + 2048)              /* 230400: 512 int             */
#define SMEM_TOTAL (SM_HIST + 2048)           /* 232448 = 227 KB max         */

__device__ int   g_counts[KCODES];
__device__ float g_msep[NCTA];

__device__ __forceinline__ uint32_t f2tf32(float v) {
    uint32_t r;
    asm("cvt.rna.tf32.f32 %0, %1;" : "=r"(r) : "f"(v));
    return r;
}
__device__ __forceinline__ void tf32split(float v, uint32_t& h, uint32_t& l) {
    h = f2tf32(v);
    l = f2tf32(v - __uint_as_float(h));
}

__device__ __forceinline__ void mma_tf32(float c[4], const uint32_t a[4],
                                         uint32_t b0, uint32_t b1)
{
    asm volatile(
        "mma.sync.aligned.m16n8k8.row.col.f32.tf32.tf32.f32 "
        "{%0,%1,%2,%3}, {%4,%5,%6,%7}, {%8,%9}, {%0,%1,%2,%3};"
        : "+f"(c[0]), "+f"(c[1]), "+f"(c[2]), "+f"(c[3])
        : "r"(a[0]), "r"(a[1]), "r"(a[2]), "r"(a[3]), "r"(b0), "r"(b1));
}

__global__ void __launch_bounds__(KCODES, 1) vq_init()
{
    g_counts[threadIdx.x] = 0;
}

/* ---------------- main (persistent, 148 CTAs x 512 thr) ---------------- */
__global__ void __launch_bounds__(TPB, 1)
vq_main(const float* __restrict__ x, const float* __restrict__ w,
        float* __restrict__ out)
{
    extern __shared__ char smem[];
    float*          s_wsq  = (float*)(smem + SM_WSQ);
    float*          s_sx   = (float*)(smem + SM_SX);
    float*          s_best = (float*)(smem + SM_BEST);
    unsigned short* s_idx  = (unsigned short*)(smem + SM_IDX);
    int*            s_hist = (int*)(smem + SM_HIST);
    float*          s_red  = (float*)(smem + SM_SX);   /* alias: sx dead then */

    const int tid  = threadIdx.x;
    const int wid  = tid >> 5;
    const int lane = tid & 31;
    const int qr   = lane >> 2;
    const int qp   = lane & 3;
    const int bid  = blockIdx.x;

    for (int i = tid; i < KCODES; i += TPB) s_hist[i] = 0;
    for (int i = tid; i < MAXSLOT * TILE_M; i += TPB) {
        s_best[i] = __int_as_float(0x7f800000);
        s_idx[i]  = 0;
    }
    /* wsq: one row per thread, sequential fmaf chain (matches ref) */
    {
        const float* wr = w + (size_t)tid * DIM;
        float sq = 0.f;
        #pragma unroll
        for (int c = 0; c < DIM; c++) sq = fmaf(wr[c], wr[c], sq);
        s_wsq[tid] = sq;
    }
    __syncthreads();

    int nslots = 0;

    #pragma unroll 1
    for (int half = 0; half < 2; half++) {
        const int nbase = half * NHALF;

        /* ---- pack B half: tf32 split quads {bh,bh+4,bl,bl+4} ---- */
        if (tid < NHALF) {
            const float* wr = w + (size_t)(nbase + tid) * DIM;
            float4* br = (float4*)(smem + SM_B + (size_t)tid * 576);
            #pragma unroll
            for (int k = 0; k < 8; k++) {
                float4 v0 = *(const float4*)(wr + k * 8);
                float4 v1 = *(const float4*)(wr + k * 8 + 4);
                uint32_t h0, l0, h1, l1;
                tf32split(v0.x, h0, l0); tf32split(v1.x, h1, l1);
                br[k * 4 + 0] = make_float4(__uint_as_float(h0), __uint_as_float(h1),
                                            __uint_as_float(l0), __uint_as_float(l1));
                tf32split(v0.y, h0, l0); tf32split(v1.y, h1, l1);
                br[k * 4 + 1] = make_float4(__uint_as_float(h0), __uint_as_float(h1),
                                            __uint_as_float(l0), __uint_as_float(l1));
                tf32split(v0.z, h0, l0); tf32split(v1.z, h1, l1);
                br[k * 4 + 2] = make_float4(__uint_as_float(h0), __uint_as_float(h1),
                                            __uint_as_float(l0), __uint_as_float(l1));
                tf32split(v0.w, h0, l0); tf32split(v1.w, h1, l1);
                br[k * 4 + 3] = make_float4(__uint_as_float(h0), __uint_as_float(h1),
                                            __uint_as_float(l0), __uint_as_float(l1));
            }
        }
        __syncthreads();

        int slot = 0;
        #pragma unroll 1
        for (int tile = bid; tile < NTILES; tile += NCTA, slot++) {
            const int T0 = tile * TILE_M;

            /* ---- gather tokens (threads 0..255), raw pairs + s chain ---- */
            if (tid < TILE_M) {
                const int b  = T0 >> 12;
                const int hw = (T0 & 4095) + tid;
                const float* xb = x + (size_t)b * (DIM * 4096) + hw;
                float2* ar = (float2*)(smem + SM_A + (size_t)tid * 288);
                float s = 0.f;
                #pragma unroll
                for (int g8 = 0; g8 < 8; g8++) {
                    float v[8];
                    #pragma unroll
                    for (int j = 0; j < 8; j++)
                        v[j] = xb[(size_t)(g8 * 8 + j) * 4096];
                    #pragma unroll
                    for (int j = 0; j < 8; j++) s = fmaf(v[j], v[j], s);
                    #pragma unroll
                    for (int j = 0; j < 4; j++)
                        ar[g8 * 4 + j] = make_float2(v[j], v[j + 4]);
                }
                s_sx[tid] = s;
            }
            __syncthreads();

            /* ---- warp stripe: 16 tokens x 256 codes (this half) ---- */
            {
                const int r0 = wid * 16 + qr, r1 = r0 + 8;
                const float2* pa0 = (const float2*)(smem + SM_A + (size_t)r0 * 288) + qp;
                const float2* pa1 = (const float2*)(smem + SM_A + (size_t)r1 * 288) + qp;

                uint32_t Ah[8][4], Al[8][4];
                #pragma unroll
                for (int k = 0; k < 8; k++) {
                    float2 p0 = pa0[k * 4];
                    float2 p1 = pa1[k * 4];
                    tf32split(p0.x, Ah[k][0], Al[k][0]);
                    tf32split(p1.x, Ah[k][1], Al[k][1]);
                    tf32split(p0.y, Ah[k][2], Al[k][2]);
                    tf32split(p1.y, Ah[k][3], Al[k][3]);
                }

                const float sx0 = s_sx[r0];
                const float sx1 = s_sx[r1];
                float best0 = __int_as_float(0x7f800000), best1 = best0;
                int   bi0 = 0, bi1 = 0;

                #pragma unroll 2
                for (int n0 = 0; n0 < NHALF; n0 += 8) {
                    float c0[4] = {0.f, 0.f, 0.f, 0.f};
                    float c1[4] = {0.f, 0.f, 0.f, 0.f};
                    float c2[4] = {0.f, 0.f, 0.f, 0.f};
                    const uint4* pb =
                        (const uint4*)(smem + SM_B + (size_t)(n0 + qr) * 576) + qp;
                    #pragma unroll
                    for (int k = 0; k < 8; k++) {
                        uint4 q = pb[k * 4];           /* {bh0,bh1,bl0,bl1} */
                        mma_tf32(c0, Ah[k], q.x, q.y); /* hi*hi */
                        mma_tf32(c1, Al[k], q.x, q.y); /* lo*hi */
                        mma_tf32(c2, Ah[k], q.z, q.w); /* hi*lo */
                    }
                    const int gj = nbase + n0 + 2 * qp;
                    const float2 wsq2 = *(const float2*)(s_wsq + gj);
                    const float d00 = fmaf(-2.f, (c0[0] + c1[0]) + c2[0], sx0) + wsq2.x;
                    const float d01 = fmaf(-2.f, (c0[1] + c1[1]) + c2[1], sx0) + wsq2.y;
                    const float d10 = fmaf(-2.f, (c0[2] + c1[2]) + c2[2], sx1) + wsq2.x;
                    const float d11 = fmaf(-2.f, (c0[3] + c1[3]) + c2[3], sx1) + wsq2.y;
                    if (d00 < best0) { best0 = d00; bi0 = gj; }
                    if (d01 < best0) { best0 = d01; bi0 = gj + 1; }
                    if (d10 < best1) { best1 = d10; bi1 = gj; }
                    if (d11 < best1) { best1 = d11; bi1 = gj + 1; }
                }

                /* cross-quad reduce, first-index tie-break */
                #pragma unroll
                for (int o = 1; o <= 2; o <<= 1) {
                    float ob0 = __shfl_xor_sync(0xffffffffu, best0, o);
                    int   oi0 = __shfl_xor_sync(0xffffffffu, bi0, o);
                    float ob1 = __shfl_xor_sync(0xffffffffu, best1, o);
                    int   oi1 = __shfl_xor_sync(0xffffffffu, bi1, o);
                    if (ob0 < best0 || (ob0 == best0 && oi0 < bi0)) { best0 = ob0; bi0 = oi0; }
                    if (ob1 < best1 || (ob1 == best1 && oi1 < bi1)) { best1 = ob1; bi1 = oi1; }
                }
                /* merge with running best (halves ascend: ties keep stored) */
                if (qp == 0) {
                    const int o0 = slot * TILE_M + r0;
                    const int o1 = slot * TILE_M + r1;
                    if (best0 < s_best[o0]) { s_best[o0] = best0; s_idx[o0] = (unsigned short)bi0; }
                    if (best1 < s_best[o1]) { s_best[o1] = best1; s_idx[o1] = (unsigned short)bi1; }
                }
            }
            __syncthreads();
        }
        nslots = slot;
    }

    /* ---- epilogue: out = x_lin + (w[idx]-x_lin), fused MSE + hist ---- */
    float mse_acc = 0.f;
    #pragma unroll 1
    for (int slot = 0; slot < nslots; slot++) {
        const int T0 = (bid + slot * NCTA) * TILE_M;
        if (tid < TILE_M) {
            const int g    = T0 + tid;
            const int bidx = (int)s_idx[slot * TILE_M + tid];
            const float4* wb = (const float4*)(w + (size_t)bidx * DIM);
            const float4* xl = (const float4*)(x + (size_t)g * DIM);
            float4*       o4 = (float4*)(out + (size_t)g * DIM);
            float mse = 0.f;
            #pragma unroll
            for (int i = 0; i < DIM / 4; i++) {
                float4 wv = wb[i];
                float4 xv = xl[i];
                float d0 = wv.x - xv.x, d1 = wv.y - xv.y;
                float d2 = wv.z - xv.z, d3 = wv.w - xv.w;
                mse = fmaf(d0, d0, mse); mse = fmaf(d1, d1, mse);
                mse = fmaf(d2, d2, mse); mse = fmaf(d3, d3, mse);
                float4 ov;
                ov.x = xv.x + d0; ov.y = xv.y + d1;
                ov.z = xv.z + d2; ov.w = xv.w + d3;
                o4[i] = ov;
            }
            mse_acc += mse;
            atomicAdd(&s_hist[bidx], 1);
        }
    }
    __syncthreads();   /* sx dead -> s_red alias safe */

    /* ---- block MSE reduce (warps 0..7 hold data) ---- */
    #pragma unroll
    for (int o = 16; o > 0; o >>= 1)
        mse_acc += __shfl_xor_sync(0xffffffffu, mse_acc, o);
    if (lane == 0) s_red[wid] = mse_acc;
    __syncthreads();
    if (tid == 0) {
        float t = 0.f;
        #pragma unroll
        for (int i = 0; i < TPB / 32; i++) t += s_red[i];
        g_msep[bid] = t;
    }

    /* ---- flush histogram ---- */
    for (int i = tid; i < KCODES; i += TPB) {
        int c = s_hist[i];
        if (c) atomicAdd(&g_counts[i], c);
    }
}

/* ---------------- final scalars ---------------- */
__global__ void __launch_bounds__(512, 1)
vq_final(float* __restrict__ out)
{
    __shared__ float sred[16];
    const int tid = threadIdx.x;

    float m = (tid < NCTA) ? g_msep[tid] : 0.f;
    #pragma unroll
    for (int o = 16; o > 0; o >>= 1)
        m += __shfl_xor_sync(0xffffffffu, m, o);
    if ((tid & 31) == 0) sred[tid >> 5] = m;
    __syncthreads();
    float mt = 0.f;
    if (tid == 0) {
        #pragma unroll
        for (int i = 0; i < 16; i++) mt += sred[i];
    }
    __syncthreads();

    float p = (float)g_counts[tid] * (1.0f / (float)TOKENS);
    float e = p * logf(p + 1e-10f);
    #pragma unroll
    for (int o = 16; o > 0; o >>= 1)
        e += __shfl_xor_sync(0xffffffffu, e, o);
    if ((tid & 31) == 0) sred[tid >> 5] = e;
    __syncthreads();
    if (tid == 0) {
        float et = 0.f;
        #pragma unroll
        for (int i = 0; i < 16; i++) et += sred[i];
        out[(size_t)TOKENS * DIM]     = 1.25f * (mt / (float)(TOKENS * DIM));
        out[(size_t)TOKENS * DIM + 1] = expf(-et);
    }
}

extern "C" void kernel_launch(void* const* d_in, const int* in_sizes, int n_in,
                              void* d_out, int out_size)
{
    const float* x = (const float*)d_in[0];
    const float* w = (const float*)d_in[1];
    if (n_in >= 2 && in_sizes[0] == KCODES * DIM && in_sizes[1] == TOKENS * DIM) {
        const float* t = x; x = w; w = t;
    }
    float* out = (float*)d_out;

    (void)cudaFuncSetAttribute(vq_main,
                               cudaFuncAttributeMaxDynamicSharedMemorySize,
                               SMEM_TOTAL);

    vq_init<<<1, KCODES>>>();
    vq_main<<<NCTA, TPB, SMEM_TOTAL>>>(x, w, out);
    vq_final<<<1, 512>>>(out);
}